// round 13
// baseline (speedup 1.0000x reference)
#include <cuda_runtime.h>
#include <cuda_bf16.h>
#include <cstdint>

// ---------------- problem constants ----------------
#define NTOK   4096
#define DDIM   1024
#define HDIM   4096
#define NEXP   8
#define NSLOTS (NTOK*2)
#define MAXSLOTS 9216            // 8192 + 8*128 pad headroom
#define MTILES (MAXSLOTS/128)    // 72

// ---------------- device scratch ----------------
__device__ float g_probs[NTOK*NEXP];
__device__ int   g_eidx[NSLOTS];
__device__ float g_rw[NSLOTS];
__device__ int   g_counts[NEXP];
__device__ int   g_fill[NEXP];
__device__ int   g_offpad[NEXP+1];
__device__ int   g_list[MAXSLOTS];
__device__ float g_ws[MAXSLOTS];
__device__ int   g_sexp[MAXSLOTS];
__device__ int   g_tokslot[NSLOTS];
__device__ __nv_bfloat16 g_xhi[(size_t)NTOK*DDIM];
__device__ __nv_bfloat16 g_xlo[(size_t)NTOK*DDIM];
__device__ __nv_bfloat16 g_wfchi[(size_t)NEXP*HDIM*DDIM];
__device__ __nv_bfloat16 g_wfclo[(size_t)NEXP*HDIM*DDIM];
__device__ __nv_bfloat16 g_wphi[(size_t)NEXP*DDIM*HDIM];
__device__ __nv_bfloat16 g_wplo[(size_t)NEXP*DDIM*HDIM];
__device__ __nv_bfloat16 g_hhi[(size_t)MAXSLOTS*HDIM];
__device__ __nv_bfloat16 g_hlo[(size_t)MAXSLOTS*HDIM];
__device__ float g_outslot[(size_t)MAXSLOTS*DDIM];

// ---------------- PTX helpers ----------------
__device__ __forceinline__ uint32_t smem_u32(const void* p) {
    uint32_t a;
    asm("{ .reg .u64 t; cvta.to.shared.u64 t, %1; cvt.u32.u64 %0, t; }" : "=r"(a) : "l"(p));
    return a;
}
__device__ __forceinline__ void cp_async16(uint32_t dst, const void* src) {
    asm volatile("cp.async.cg.shared.global [%0], [%1], 16;" :: "r"(dst), "l"(src));
}
#define CP_COMMIT() asm volatile("cp.async.commit_group;" ::: "memory")
#define CP_WAIT1()  asm volatile("cp.async.wait_group 1;" ::: "memory")

__device__ __forceinline__ void ldsm_x4(uint32_t* r, uint32_t addr) {
    asm volatile("ldmatrix.sync.aligned.m8n8.x4.shared.b16 {%0,%1,%2,%3}, [%4];"
                 : "=r"(r[0]), "=r"(r[1]), "=r"(r[2]), "=r"(r[3]) : "r"(addr));
}
__device__ __forceinline__ void mma16816(float* d, const uint32_t* a, const uint32_t* b) {
    asm volatile("mma.sync.aligned.m16n8k16.row.col.f32.bf16.bf16.f32 "
        "{%0,%1,%2,%3}, {%4,%5,%6,%7}, {%8,%9}, {%0,%1,%2,%3};"
        : "+f"(d[0]), "+f"(d[1]), "+f"(d[2]), "+f"(d[3])
        : "r"(a[0]), "r"(a[1]), "r"(a[2]), "r"(a[3]), "r"(b[0]), "r"(b[1]));
}

// ---------------- smem layout ----------------
#define TBUF(mat, stg) (1024 + ((mat)*3 + (stg))*8192)
#define SM_MMA_TOTAL (1024 + 12*8192)   // 99328 -> 2 CTAs/SM
#define SWZ(r, c) ((uint32_t)((r)*64 + (((c) ^ (((r)>>1)&3))<<4)))

// ---------------- fp32 -> bf16 hi/lo split, 4 float4 per thread (MLP=4) -----
__global__ void cvt_kernel(const float* __restrict__ src, __nv_bfloat16* __restrict__ hi,
                           __nv_bfloat16* __restrict__ lo, int n4) {
    int i0 = (blockIdx.x*blockDim.x + threadIdx.x) * 4;
    if (i0 + 3 >= n4) {  // tail (never taken for our sizes, kept for safety)
        for (int i = i0; i < n4; i++) {
            float4 v = ((const float4*)src)[i];
            __nv_bfloat16 h0 = __float2bfloat16(v.x);
            __nv_bfloat16 h1 = __float2bfloat16(v.y);
            __nv_bfloat16 h2 = __float2bfloat16(v.z);
            __nv_bfloat16 h3 = __float2bfloat16(v.w);
            __nv_bfloat162 a, b;
            a.x = h0; a.y = h1; b.x = h2; b.y = h3;
            ((__nv_bfloat162*)hi)[i*2] = a; ((__nv_bfloat162*)hi)[i*2+1] = b;
            a.x = __float2bfloat16(v.x - __bfloat162float(h0));
            a.y = __float2bfloat16(v.y - __bfloat162float(h1));
            b.x = __float2bfloat16(v.z - __bfloat162float(h2));
            b.y = __float2bfloat16(v.w - __bfloat162float(h3));
            ((__nv_bfloat162*)lo)[i*2] = a; ((__nv_bfloat162*)lo)[i*2+1] = b;
        }
        return;
    }
    float4 v[4];
    #pragma unroll
    for (int j = 0; j < 4; j++) v[j] = ((const float4*)src)[i0 + j];  // 4 independent LDGs
    #pragma unroll
    for (int j = 0; j < 4; j++) {
        int i = i0 + j;
        __nv_bfloat16 h0 = __float2bfloat16(v[j].x);
        __nv_bfloat16 h1 = __float2bfloat16(v[j].y);
        __nv_bfloat16 h2 = __float2bfloat16(v[j].z);
        __nv_bfloat16 h3 = __float2bfloat16(v[j].w);
        __nv_bfloat162 a, b;
        a.x = h0; a.y = h1; b.x = h2; b.y = h3;
        ((__nv_bfloat162*)hi)[i*2] = a; ((__nv_bfloat162*)hi)[i*2+1] = b;
        a.x = __float2bfloat16(v[j].x - __bfloat162float(h0));
        a.y = __float2bfloat16(v[j].y - __bfloat162float(h1));
        b.x = __float2bfloat16(v[j].z - __bfloat162float(h2));
        b.y = __float2bfloat16(v[j].w - __bfloat162float(h3));
        ((__nv_bfloat162*)lo)[i*2] = a; ((__nv_bfloat162*)lo)[i*2+1] = b;
    }
}

// ---------------- zero counters ----------------
__global__ void zero_kernel() {
    int i = threadIdx.x;
    if (i < NEXP) { g_counts[i] = 0; g_fill[i] = 0; }
}

// ---------------- gating + x split + global expert counts ----------------
__global__ void gate_kernel(const float* __restrict__ x, const float* __restrict__ Wg) {
    int n = blockIdx.x;
    int tid = threadIdx.x;
    int w = tid >> 5, lane = tid & 31;
    const float4* xr = (const float4*)(x + (size_t)n * DDIM);
    const float4* gr = (const float4*)(Wg + (size_t)w * DDIM);
    float s = 0.0f;
    #pragma unroll 4
    for (int i = lane; i < DDIM/4; i += 32) {
        float4 a = xr[i], b = gr[i];
        s += a.x*b.x + a.y*b.y + a.z*b.z + a.w*b.w;
    }
    {
        float4 v = xr[tid];
        __nv_bfloat16 h0 = __float2bfloat16(v.x); __nv_bfloat16 l0 = __float2bfloat16(v.x - __bfloat162float(h0));
        __nv_bfloat16 h1 = __float2bfloat16(v.y); __nv_bfloat16 l1 = __float2bfloat16(v.y - __bfloat162float(h1));
        __nv_bfloat16 h2 = __float2bfloat16(v.z); __nv_bfloat16 l2 = __float2bfloat16(v.z - __bfloat162float(h2));
        __nv_bfloat16 h3 = __float2bfloat16(v.w); __nv_bfloat16 l3 = __float2bfloat16(v.w - __bfloat162float(h3));
        __nv_bfloat162 a2, b2;
        a2.x = h0; a2.y = h1; b2.x = h2; b2.y = h3;
        size_t base2 = ((size_t)n * DDIM)/2 + tid*2;
        ((__nv_bfloat162*)g_xhi)[base2] = a2; ((__nv_bfloat162*)g_xhi)[base2+1] = b2;
        a2.x = l0; a2.y = l1; b2.x = l2; b2.y = l3;
        ((__nv_bfloat162*)g_xlo)[base2] = a2; ((__nv_bfloat162*)g_xlo)[base2+1] = b2;
    }
    #pragma unroll
    for (int o = 16; o; o >>= 1) s += __shfl_xor_sync(0xFFFFFFFFu, s, o);
    __shared__ float logits[NEXP];
    if (lane == 0) logits[w] = s;
    __syncthreads();
    if (tid == 0) {
        float m = logits[0];
        #pragma unroll
        for (int e = 1; e < NEXP; e++) m = fmaxf(m, logits[e]);
        float p[NEXP]; float sum = 0.0f;
        #pragma unroll
        for (int e = 0; e < NEXP; e++) { p[e] = expf(logits[e] - m); sum += p[e]; }
        float inv = 1.0f / sum;
        #pragma unroll
        for (int e = 0; e < NEXP; e++) { p[e] *= inv; g_probs[n*NEXP + e] = p[e]; }
        int i1 = 0;
        #pragma unroll
        for (int e = 1; e < NEXP; e++) if (p[e] > p[i1]) i1 = e;
        int i2 = -1;
        #pragma unroll
        for (int e = 0; e < NEXP; e++) {
            if (e == i1) continue;
            if (i2 < 0 || p[e] > p[i2]) i2 = e;
        }
        float r = 1.0f / (p[i1] + p[i2]);
        g_eidx[n*2]   = i1;  g_eidx[n*2+1] = i2;
        g_rw[n*2]     = p[i1]*r;  g_rw[n*2+1] = p[i2]*r;
        atomicAdd(&g_counts[i1], 1);
        atomicAdd(&g_counts[i2], 1);
    }
}

// ------- offsets: padded segment bases + pad-slot init (1 small block) ------
__global__ void offsets_kernel() {
    __shared__ int base[NEXP], cnt[NEXP], seg_end[NEXP];
    int tid = threadIdx.x;
    if (tid == 0) {
        int off = 0;
        for (int e = 0; e < NEXP; e++) {
            int c = g_counts[e];
            cnt[e] = c;
            g_offpad[e] = off;
            base[e] = off;
            off += ((c + 127) >> 7) << 7;
            seg_end[e] = off;
        }
        g_offpad[NEXP] = off;
    }
    __syncthreads();
    for (int e = 0; e < NEXP; e++) {
        for (int s = base[e] + cnt[e] + tid; s < seg_end[e]; s += 256) {
            g_list[s] = 0; g_ws[s] = 0.0f; g_sexp[s] = e;
        }
    }
}

// ---------------- scatter (multi-block, global fill atomics) ----------------
__global__ void scatter_kernel() {
    int i = blockIdx.x*blockDim.x + threadIdx.x;
    if (i >= NSLOTS) return;
    int e = g_eidx[i];
    int pos = atomicAdd(&g_fill[e], 1);
    int slot = g_offpad[e] + pos;
    g_list[slot] = i >> 1;
    g_ws[slot] = g_rw[i];
    g_sexp[slot] = e;
    g_tokslot[i] = slot;
}

// ---------------- bf16-split HMMA GEMM (unchanged from 1126.8us winner) -----
template<bool IS_FC>
__global__ void __launch_bounds__(256, 2) mma_kernel() {
    extern __shared__ char smem[];
    const uint32_t sbase = smem_u32(smem);
    const int tid = threadIdx.x;
    const int lane = tid & 31;
    const int wrp = tid >> 5;
    const int wm = wrp >> 2;
    const int wn = wrp & 3;
    const int slot0 = blockIdx.x * 128;
    const int nb   = blockIdx.y * 128;
    const int KDIM = IS_FC ? DDIM : HDIM;
    const int NITER = KDIM / 32;

    if (slot0 >= g_offpad[NEXP]) return;

    int* rowtok_s = (int*)smem;
    float* roww_s = (float*)(smem + 512);
    if (tid < 128) {
        rowtok_s[tid] = g_list[slot0 + tid];
        roww_s[tid]   = g_ws[slot0 + tid];
    }
    __syncthreads();

    const int e = g_sexp[slot0];
    const __nv_bfloat16 *Ah, *Al, *Bh, *Bl;
    if (IS_FC) {
        Ah = g_xhi;  Al = g_xlo;
        Bh = g_wfchi + ((size_t)e*HDIM + nb) * DDIM;
        Bl = g_wfclo + ((size_t)e*HDIM + nb) * DDIM;
    } else {
        Ah = g_hhi + (size_t)slot0 * HDIM;
        Al = g_hlo + (size_t)slot0 * HDIM;
        Bh = g_wphi + ((size_t)e*DDIM + nb) * HDIM;
        Bl = g_wplo + ((size_t)e*DDIM + nb) * HDIM;
    }

    const int c0r = tid >> 2, c0s = tid & 3;
    size_t arow0, arow1;
    if (IS_FC) { arow0 = (size_t)rowtok_s[c0r] * DDIM; arow1 = (size_t)rowtok_s[c0r + 64] * DDIM; }
    else       { arow0 = (size_t)c0r * HDIM;           arow1 = (size_t)(c0r + 64) * HDIM; }
    const size_t brow0 = (size_t)c0r * KDIM, brow1 = (size_t)(c0r + 64) * KDIM;
    const uint32_t soff0 = SWZ(c0r, c0s);
    const uint32_t soff1 = soff0 + 64*64;

    auto issue_load = [&](int stg, int k0) {
        size_t col = (size_t)k0 + c0s*8;
        cp_async16(sbase + TBUF(0,stg) + soff0, Ah + arow0 + col);
        cp_async16(sbase + TBUF(0,stg) + soff1, Ah + arow1 + col);
        cp_async16(sbase + TBUF(1,stg) + soff0, Al + arow0 + col);
        cp_async16(sbase + TBUF(1,stg) + soff1, Al + arow1 + col);
        cp_async16(sbase + TBUF(2,stg) + soff0, Bh + brow0 + col);
        cp_async16(sbase + TBUF(2,stg) + soff1, Bh + brow1 + col);
        cp_async16(sbase + TBUF(3,stg) + soff0, Bl + brow0 + col);
        cp_async16(sbase + TBUF(3,stg) + soff1, Bl + brow1 + col);
    };

    float acc[4][4][4];
    #pragma unroll
    for (int mt = 0; mt < 4; mt++)
        #pragma unroll
        for (int nt = 0; nt < 4; nt++)
            #pragma unroll
            for (int j = 0; j < 4; j++) acc[mt][nt][j] = 0.0f;

    issue_load(0, 0);  CP_COMMIT();
    issue_load(1, 32); CP_COMMIT();

    uint32_t a_rb[4], a_sw[4];
    #pragma unroll
    for (int mt = 0; mt < 4; mt++) {
        uint32_t r = (uint32_t)(wm*64 + mt*16 + (lane & 15));
        a_rb[mt] = r * 64;
        a_sw[mt] = (r >> 1) & 3;
    }
    const uint32_t a_ck = (uint32_t)(lane >> 4);

    uint32_t b_rb[2], b_sw[2];
    #pragma unroll
    for (int p = 0; p < 2; p++) {
        uint32_t r = (uint32_t)(wn*32 + p*16 + (lane & 7) + ((lane >> 4) << 3));
        b_rb[p] = r * 64;
        b_sw[p] = (r >> 1) & 3;
    }
    const uint32_t b_ck = (uint32_t)((lane >> 3) & 1);

    int stg = 0;
    for (int it = 0; it < NITER; it++) {
        CP_WAIT1();
        __syncthreads();
        if (it + 2 < NITER) {
            int nstg = stg + 2; if (nstg >= 3) nstg -= 3;
            issue_load(nstg, (it + 2) * 32);
        }
        CP_COMMIT();

        const uint32_t bAh = sbase + TBUF(0,stg);
        const uint32_t bAl = sbase + TBUF(1,stg);
        const uint32_t bBh = sbase + TBUF(2,stg);
        const uint32_t bBl = sbase + TBUF(3,stg);
        #pragma unroll
        for (int ks = 0; ks < 2; ks++) {
            uint32_t ahi[4][4], alo[4][4];
            #pragma unroll
            for (int mt = 0; mt < 4; mt++) {
                uint32_t off = a_rb[mt] + (((ks*2 + a_ck) ^ a_sw[mt]) << 4);
                ldsm_x4(ahi[mt], bAh + off);
                ldsm_x4(alo[mt], bAl + off);
            }
            #pragma unroll
            for (int p = 0; p < 2; p++) {
                uint32_t off = b_rb[p] + (((ks*2 + b_ck) ^ b_sw[p]) << 4);
                uint32_t bh4[4], bl4[4];
                ldsm_x4(bh4, bBh + off);
                ldsm_x4(bl4, bBl + off);
                #pragma unroll
                for (int q = 0; q < 2; q++)
                    #pragma unroll
                    for (int mt = 0; mt < 4; mt++)
                        mma16816(acc[mt][p*2+q], ahi[mt], bh4 + q*2);
                #pragma unroll
                for (int q = 0; q < 2; q++)
                    #pragma unroll
                    for (int mt = 0; mt < 4; mt++)
                        mma16816(acc[mt][p*2+q], ahi[mt], bl4 + q*2);
                #pragma unroll
                for (int q = 0; q < 2; q++)
                    #pragma unroll
                    for (int mt = 0; mt < 4; mt++)
                        mma16816(acc[mt][p*2+q], alo[mt], bh4 + q*2);
            }
        }
        stg++; if (stg >= 3) stg = 0;
    }

    #pragma unroll
    for (int mt = 0; mt < 4; mt++) {
        #pragma unroll
        for (int nt = 0; nt < 4; nt++) {
            int r0 = wm*64 + mt*16 + (lane >> 2);
            int c0 = wn*32 + nt*8 + (lane & 3)*2;
            #pragma unroll
            for (int half = 0; half < 2; half++) {
                int r = r0 + half*8;
                float d0 = acc[mt][nt][half*2];
                float d1 = acc[mt][nt][half*2 + 1];
                if (IS_FC) {
                    float wv = roww_s[r];
                    float v0 = fmaxf(d0, 0.0f); v0 = v0*v0*wv;
                    float v1 = fmaxf(d1, 0.0f); v1 = v1*v1*wv;
                    __nv_bfloat16 h0 = __float2bfloat16(v0);
                    __nv_bfloat16 l0 = __float2bfloat16(v0 - __bfloat162float(h0));
                    __nv_bfloat16 h1 = __float2bfloat16(v1);
                    __nv_bfloat16 l1 = __float2bfloat16(v1 - __bfloat162float(h1));
                    __nv_bfloat162 hh; hh.x = h0; hh.y = h1;
                    __nv_bfloat162 ll; ll.x = l0; ll.y = l1;
                    size_t base = (size_t)(slot0 + r)*HDIM + nb + c0;
                    *(__nv_bfloat162*)(g_hhi + base) = hh;
                    *(__nv_bfloat162*)(g_hlo + base) = ll;
                } else {
                    size_t base = (size_t)(slot0 + r)*DDIM + nb + c0;
                    float2 o; o.x = d0; o.y = d1;
                    *(float2*)(g_outslot + base) = o;
                }
            }
        }
    }
}

// ---------------- combine ----------------
__global__ void combine_kernel(float* __restrict__ out) {
    int n = blockIdx.x;
    int tid = threadIdx.x;
    int s0 = g_tokslot[n*2], s1 = g_tokslot[n*2+1];
    const float4* a = (const float4*)(g_outslot + (size_t)s0 * DDIM);
    const float4* b = (const float4*)(g_outslot + (size_t)s1 * DDIM);
    float4* o = (float4*)(out + (size_t)n * DDIM);
    for (int d = tid; d < DDIM/4; d += 256) {
        float4 av = a[d], bv = b[d];
        float4 ov;
        ov.x = av.x + bv.x; ov.y = av.y + bv.y;
        ov.z = av.z + bv.z; ov.w = av.w + bv.w;
        o[d] = ov;
    }
}

// ---------------- balance loss ----------------
__global__ void loss_kernel(float* __restrict__ out, int write_loss) {
    __shared__ float red[256];
    __shared__ float acc_sh;
    int tid = threadIdx.x;
    if (tid == 0) acc_sh = 0.0f;
    __syncthreads();
    for (int e = 0; e < NEXP; e++) {
        float s = 0.0f;
        for (int n = tid; n < NTOK; n += 256) s += g_probs[n*NEXP + e];
        red[tid] = s;
        __syncthreads();
        for (int o = 128; o; o >>= 1) {
            if (tid < o) red[tid] += red[tid + o];
            __syncthreads();
        }
        if (tid == 0) {
            float meanp = red[0] / (float)NTOK;
            float freq = (float)g_counts[e] / (float)NTOK;
            acc_sh += meanp * freq;
        }
        __syncthreads();
    }
    if (tid == 0 && write_loss)
        out[(size_t)NTOK * DDIM] = acc_sh * (float)NEXP;
}

// ---------------- launch (single stream; overlap proven dead) ----------------
extern "C" void kernel_launch(void* const* d_in, const int* in_sizes, int n_in,
                              void* d_out, int out_size) {
    const float* x   = (const float*)d_in[0];
    const float* Wg  = (const float*)d_in[1];
    const float* Wfc = (const float*)d_in[2];
    const float* Wp  = (const float*)d_in[3];
    float* out = (float*)d_out;

    cudaFuncSetAttribute(mma_kernel<true>,  cudaFuncAttributeMaxDynamicSharedMemorySize, SM_MMA_TOTAL);
    cudaFuncSetAttribute(mma_kernel<false>, cudaFuncAttributeMaxDynamicSharedMemorySize, SM_MMA_TOTAL);

    __nv_bfloat16 *wfchi, *wfclo, *wphi, *wplo;
    cudaGetSymbolAddress((void**)&wfchi, g_wfchi);
    cudaGetSymbolAddress((void**)&wfclo, g_wfclo);
    cudaGetSymbolAddress((void**)&wphi,  g_wphi);
    cudaGetSymbolAddress((void**)&wplo,  g_wplo);

    int n4w = NEXP*HDIM*DDIM/4;
    int cvtBlocks = (n4w/4 + 255)/256;

    zero_kernel<<<1, 32>>>();                                      // 0
    cvt_kernel<<<cvtBlocks, 256>>>(Wfc, wfchi, wfclo, n4w);        // 1
    gate_kernel<<<NTOK, 256>>>(x, Wg);                             // 2 (x split + counts)
    offsets_kernel<<<1, 256>>>();                                  // 3 (pads init)
    scatter_kernel<<<(NSLOTS + 255)/256, 256>>>();                 // 4
    dim3 gfc(MTILES, HDIM/128);
    mma_kernel<true><<<gfc, 256, SM_MMA_TOTAL>>>();                // 5
    cvt_kernel<<<cvtBlocks, 256>>>(Wp,  wphi,  wplo,  n4w);        // 6
    dim3 gpj(MTILES, DDIM/128);
    mma_kernel<false><<<gpj, 256, SM_MMA_TOTAL>>>();               // 7
    combine_kernel<<<NTOK, 256>>>(out);                            // 8
    int write_loss = (out_size > NTOK*DDIM) ? 1 : 0;
    loss_kernel<<<1, 256>>>(out, write_loss);                      // 9
}

// round 16
// speedup vs baseline: 1.1630x; 1.1630x over previous
#include <cuda_runtime.h>
#include <cuda_bf16.h>
#include <cstdint>

// ---------------- problem constants ----------------
#define NTOK   4096
#define DDIM   1024
#define HDIM   4096
#define NEXP   8
#define NSLOTS (NTOK*2)
#define MAXSLOTS 9216            // 8192 + 8*128 pad headroom
#define MTILES (MAXSLOTS/128)    // 72

// ---------------- device scratch ----------------
__device__ float g_probs[NTOK*NEXP];
__device__ int   g_eidx[NSLOTS];
__device__ float g_rw[NSLOTS];
__device__ int   g_counts[NEXP];
__device__ int   g_offpad[NEXP+1];
__device__ int   g_list[MAXSLOTS];
__device__ float g_ws[MAXSLOTS];
__device__ int   g_sexp[MAXSLOTS];
__device__ int   g_tokslot[NSLOTS];
__device__ __nv_bfloat16 g_xhi[(size_t)NTOK*DDIM];
__device__ __nv_bfloat16 g_xlo[(size_t)NTOK*DDIM];
__device__ __nv_bfloat16 g_wfchi[(size_t)NEXP*HDIM*DDIM];
__device__ __nv_bfloat16 g_wfclo[(size_t)NEXP*HDIM*DDIM];
__device__ __nv_bfloat16 g_wphi[(size_t)NEXP*DDIM*HDIM];
__device__ __nv_bfloat16 g_wplo[(size_t)NEXP*DDIM*HDIM];
__device__ __nv_bfloat16 g_hhi[(size_t)MAXSLOTS*HDIM];
__device__ __nv_bfloat16 g_hlo[(size_t)MAXSLOTS*HDIM];
__device__ float g_outslot[(size_t)MAXSLOTS*DDIM];

// ---------------- PTX helpers ----------------
__device__ __forceinline__ uint32_t smem_u32(const void* p) {
    uint32_t a;
    asm("{ .reg .u64 t; cvta.to.shared.u64 t, %1; cvt.u32.u64 %0, t; }" : "=r"(a) : "l"(p));
    return a;
}
__device__ __forceinline__ void cp_async16(uint32_t dst, const void* src) {
    asm volatile("cp.async.cg.shared.global [%0], [%1], 16;" :: "r"(dst), "l"(src));
}
#define CP_COMMIT() asm volatile("cp.async.commit_group;" ::: "memory")
#define CP_WAIT1()  asm volatile("cp.async.wait_group 1;" ::: "memory")

__device__ __forceinline__ void ldsm_x4(uint32_t* r, uint32_t addr) {
    asm volatile("ldmatrix.sync.aligned.m8n8.x4.shared.b16 {%0,%1,%2,%3}, [%4];"
                 : "=r"(r[0]), "=r"(r[1]), "=r"(r[2]), "=r"(r[3]) : "r"(addr));
}
__device__ __forceinline__ void mma16816(float* d, const uint32_t* a, const uint32_t* b) {
    asm volatile("mma.sync.aligned.m16n8k16.row.col.f32.bf16.bf16.f32 "
        "{%0,%1,%2,%3}, {%4,%5,%6,%7}, {%8,%9}, {%0,%1,%2,%3};"
        : "+f"(d[0]), "+f"(d[1]), "+f"(d[2]), "+f"(d[3])
        : "r"(a[0]), "r"(a[1]), "r"(a[2]), "r"(a[3]), "r"(b[0]), "r"(b[1]));
}

// ---------------- smem layout ----------------
#define TBUF(mat, stg) (1024 + ((mat)*3 + (stg))*8192)
#define SM_MMA_TOTAL (1024 + 12*8192)   // 99328 -> 2 CTAs/SM
#define SWZ(r, c) ((uint32_t)((r)*64 + (((c) ^ (((r)>>1)&3))<<4)))

// ------- fp32 -> bf16 hi/lo split, grid-strided MLP=4, fully coalesced ------
__global__ void cvt_kernel(const float* __restrict__ src, __nv_bfloat16* __restrict__ hi,
                           __nv_bfloat16* __restrict__ lo, int n4) {
    const int i = blockIdx.x*blockDim.x + threadIdx.x;
    const int S = gridDim.x*blockDim.x;        // n4 == 4*S exactly for our launches
    float4 v[4];
    #pragma unroll
    for (int j = 0; j < 4; j++) v[j] = ((const float4*)src)[i + j*S];   // 4 independent, coalesced
    #pragma unroll
    for (int j = 0; j < 4; j++) {
        const int idx = i + j*S;
        __nv_bfloat16 h0 = __float2bfloat16(v[j].x);
        __nv_bfloat16 h1 = __float2bfloat16(v[j].y);
        __nv_bfloat16 h2 = __float2bfloat16(v[j].z);
        __nv_bfloat16 h3 = __float2bfloat16(v[j].w);
        __nv_bfloat162 a, b;
        a.x = h0; a.y = h1; b.x = h2; b.y = h3;
        ((__nv_bfloat162*)hi)[idx*2] = a; ((__nv_bfloat162*)hi)[idx*2+1] = b;
        a.x = __float2bfloat16(v[j].x - __bfloat162float(h0));
        a.y = __float2bfloat16(v[j].y - __bfloat162float(h1));
        b.x = __float2bfloat16(v[j].z - __bfloat162float(h2));
        b.y = __float2bfloat16(v[j].w - __bfloat162float(h3));
        ((__nv_bfloat162*)lo)[idx*2] = a; ((__nv_bfloat162*)lo)[idx*2+1] = b;
    }
}

// ---------------- gating + x split (fused) ----------------
__global__ void gate_kernel(const float* __restrict__ x, const float* __restrict__ Wg) {
    int n = blockIdx.x;
    int tid = threadIdx.x;
    int w = tid >> 5, lane = tid & 31;
    const float4* xr = (const float4*)(x + (size_t)n * DDIM);
    const float4* gr = (const float4*)(Wg + (size_t)w * DDIM);
    float s = 0.0f;
    #pragma unroll 4
    for (int i = lane; i < DDIM/4; i += 32) {
        float4 a = xr[i], b = gr[i];
        s += a.x*b.x + a.y*b.y + a.z*b.z + a.w*b.w;
    }
    {
        float4 v = xr[tid];
        __nv_bfloat16 h0 = __float2bfloat16(v.x); __nv_bfloat16 l0 = __float2bfloat16(v.x - __bfloat162float(h0));
        __nv_bfloat16 h1 = __float2bfloat16(v.y); __nv_bfloat16 l1 = __float2bfloat16(v.y - __bfloat162float(h1));
        __nv_bfloat16 h2 = __float2bfloat16(v.z); __nv_bfloat16 l2 = __float2bfloat16(v.z - __bfloat162float(h2));
        __nv_bfloat16 h3 = __float2bfloat16(v.w); __nv_bfloat16 l3 = __float2bfloat16(v.w - __bfloat162float(h3));
        __nv_bfloat162 a2, b2;
        a2.x = h0; a2.y = h1; b2.x = h2; b2.y = h3;
        size_t base2 = ((size_t)n * DDIM)/2 + tid*2;
        ((__nv_bfloat162*)g_xhi)[base2] = a2; ((__nv_bfloat162*)g_xhi)[base2+1] = b2;
        a2.x = l0; a2.y = l1; b2.x = l2; b2.y = l3;
        ((__nv_bfloat162*)g_xlo)[base2] = a2; ((__nv_bfloat162*)g_xlo)[base2+1] = b2;
    }
    #pragma unroll
    for (int o = 16; o; o >>= 1) s += __shfl_xor_sync(0xFFFFFFFFu, s, o);
    __shared__ float logits[NEXP];
    if (lane == 0) logits[w] = s;
    __syncthreads();
    if (tid == 0) {
        float m = logits[0];
        #pragma unroll
        for (int e = 1; e < NEXP; e++) m = fmaxf(m, logits[e]);
        float p[NEXP]; float sum = 0.0f;
        #pragma unroll
        for (int e = 0; e < NEXP; e++) { p[e] = expf(logits[e] - m); sum += p[e]; }
        float inv = 1.0f / sum;
        #pragma unroll
        for (int e = 0; e < NEXP; e++) { p[e] *= inv; g_probs[n*NEXP + e] = p[e]; }
        int i1 = 0;
        #pragma unroll
        for (int e = 1; e < NEXP; e++) if (p[e] > p[i1]) i1 = e;
        int i2 = -1;
        #pragma unroll
        for (int e = 0; e < NEXP; e++) {
            if (e == i1) continue;
            if (i2 < 0 || p[e] > p[i2]) i2 = e;
        }
        float r = 1.0f / (p[i1] + p[i2]);
        g_eidx[n*2]   = i1;  g_eidx[n*2+1] = i2;
        g_rw[n*2]     = p[i1]*r;  g_rw[n*2+1] = p[i2]*r;
    }
}

// ------- route: counts + offsets + scatter + pad init (1 block) -------------
__global__ void route_kernel() {
    __shared__ int cnt[NEXP];
    __shared__ int base[NEXP];
    __shared__ int seg_end[NEXP];
    int tid = threadIdx.x;
    if (tid < NEXP) cnt[tid] = 0;
    __syncthreads();
    for (int i = tid; i < NSLOTS; i += 256) atomicAdd(&cnt[g_eidx[i]], 1);
    __syncthreads();
    if (tid == 0) {
        int off = 0;
        for (int e = 0; e < NEXP; e++) {
            g_counts[e] = cnt[e];
            g_offpad[e] = off;
            base[e] = off;
            off += ((cnt[e] + 127) >> 7) << 7;
            seg_end[e] = off;
        }
        g_offpad[NEXP] = off;
    }
    __syncthreads();
    for (int e = 0; e < NEXP; e++) {
        for (int s = base[e] + cnt[e] + tid; s < seg_end[e]; s += 256) {
            g_list[s] = 0; g_ws[s] = 0.0f; g_sexp[s] = e;
        }
    }
    __syncthreads();
    if (tid < NEXP) cnt[tid] = 0;
    __syncthreads();
    for (int i = tid; i < NSLOTS; i += 256) {
        int e = g_eidx[i];
        int pos = atomicAdd(&cnt[e], 1);
        int slot = base[e] + pos;
        g_list[slot] = i >> 1;
        g_ws[slot] = g_rw[i];
        g_sexp[slot] = e;
        g_tokslot[i] = slot;
    }
}

// ---------------- bf16-split HMMA GEMM (unchanged 1126.8us champion) --------
template<bool IS_FC>
__global__ void __launch_bounds__(256, 2) mma_kernel() {
    extern __shared__ char smem[];
    const uint32_t sbase = smem_u32(smem);
    const int tid = threadIdx.x;
    const int lane = tid & 31;
    const int wrp = tid >> 5;
    const int wm = wrp >> 2;
    const int wn = wrp & 3;
    const int slot0 = blockIdx.x * 128;
    const int nb   = blockIdx.y * 128;
    const int KDIM = IS_FC ? DDIM : HDIM;
    const int NITER = KDIM / 32;

    if (slot0 >= g_offpad[NEXP]) return;

    int* rowtok_s = (int*)smem;
    float* roww_s = (float*)(smem + 512);
    if (tid < 128) {
        rowtok_s[tid] = g_list[slot0 + tid];
        roww_s[tid]   = g_ws[slot0 + tid];
    }
    __syncthreads();

    const int e = g_sexp[slot0];
    const __nv_bfloat16 *Ah, *Al, *Bh, *Bl;
    if (IS_FC) {
        Ah = g_xhi;  Al = g_xlo;
        Bh = g_wfchi + ((size_t)e*HDIM + nb) * DDIM;
        Bl = g_wfclo + ((size_t)e*HDIM + nb) * DDIM;
    } else {
        Ah = g_hhi + (size_t)slot0 * HDIM;
        Al = g_hlo + (size_t)slot0 * HDIM;
        Bh = g_wphi + ((size_t)e*DDIM + nb) * HDIM;
        Bl = g_wplo + ((size_t)e*DDIM + nb) * HDIM;
    }

    const int c0r = tid >> 2, c0s = tid & 3;
    size_t arow0, arow1;
    if (IS_FC) { arow0 = (size_t)rowtok_s[c0r] * DDIM; arow1 = (size_t)rowtok_s[c0r + 64] * DDIM; }
    else       { arow0 = (size_t)c0r * HDIM;           arow1 = (size_t)(c0r + 64) * HDIM; }
    const size_t brow0 = (size_t)c0r * KDIM, brow1 = (size_t)(c0r + 64) * KDIM;
    const uint32_t soff0 = SWZ(c0r, c0s);
    const uint32_t soff1 = soff0 + 64*64;

    auto issue_load = [&](int stg, int k0) {
        size_t col = (size_t)k0 + c0s*8;
        cp_async16(sbase + TBUF(0,stg) + soff0, Ah + arow0 + col);
        cp_async16(sbase + TBUF(0,stg) + soff1, Ah + arow1 + col);
        cp_async16(sbase + TBUF(1,stg) + soff0, Al + arow0 + col);
        cp_async16(sbase + TBUF(1,stg) + soff1, Al + arow1 + col);
        cp_async16(sbase + TBUF(2,stg) + soff0, Bh + brow0 + col);
        cp_async16(sbase + TBUF(2,stg) + soff1, Bh + brow1 + col);
        cp_async16(sbase + TBUF(3,stg) + soff0, Bl + brow0 + col);
        cp_async16(sbase + TBUF(3,stg) + soff1, Bl + brow1 + col);
    };

    float acc[4][4][4];
    #pragma unroll
    for (int mt = 0; mt < 4; mt++)
        #pragma unroll
        for (int nt = 0; nt < 4; nt++)
            #pragma unroll
            for (int j = 0; j < 4; j++) acc[mt][nt][j] = 0.0f;

    issue_load(0, 0);  CP_COMMIT();
    issue_load(1, 32); CP_COMMIT();

    uint32_t a_rb[4], a_sw[4];
    #pragma unroll
    for (int mt = 0; mt < 4; mt++) {
        uint32_t r = (uint32_t)(wm*64 + mt*16 + (lane & 15));
        a_rb[mt] = r * 64;
        a_sw[mt] = (r >> 1) & 3;
    }
    const uint32_t a_ck = (uint32_t)(lane >> 4);

    uint32_t b_rb[2], b_sw[2];
    #pragma unroll
    for (int p = 0; p < 2; p++) {
        uint32_t r = (uint32_t)(wn*32 + p*16 + (lane & 7) + ((lane >> 4) << 3));
        b_rb[p] = r * 64;
        b_sw[p] = (r >> 1) & 3;
    }
    const uint32_t b_ck = (uint32_t)((lane >> 3) & 1);

    int stg = 0;
    for (int it = 0; it < NITER; it++) {
        CP_WAIT1();
        __syncthreads();
        if (it + 2 < NITER) {
            int nstg = stg + 2; if (nstg >= 3) nstg -= 3;
            issue_load(nstg, (it + 2) * 32);
        }
        CP_COMMIT();

        const uint32_t bAh = sbase + TBUF(0,stg);
        const uint32_t bAl = sbase + TBUF(1,stg);
        const uint32_t bBh = sbase + TBUF(2,stg);
        const uint32_t bBl = sbase + TBUF(3,stg);
        #pragma unroll
        for (int ks = 0; ks < 2; ks++) {
            uint32_t ahi[4][4], alo[4][4];
            #pragma unroll
            for (int mt = 0; mt < 4; mt++) {
                uint32_t off = a_rb[mt] + (((ks*2 + a_ck) ^ a_sw[mt]) << 4);
                ldsm_x4(ahi[mt], bAh + off);
                ldsm_x4(alo[mt], bAl + off);
            }
            #pragma unroll
            for (int p = 0; p < 2; p++) {
                uint32_t off = b_rb[p] + (((ks*2 + b_ck) ^ b_sw[p]) << 4);
                uint32_t bh4[4], bl4[4];
                ldsm_x4(bh4, bBh + off);
                ldsm_x4(bl4, bBl + off);
                #pragma unroll
                for (int q = 0; q < 2; q++)
                    #pragma unroll
                    for (int mt = 0; mt < 4; mt++)
                        mma16816(acc[mt][p*2+q], ahi[mt], bh4 + q*2);
                #pragma unroll
                for (int q = 0; q < 2; q++)
                    #pragma unroll
                    for (int mt = 0; mt < 4; mt++)
                        mma16816(acc[mt][p*2+q], ahi[mt], bl4 + q*2);
                #pragma unroll
                for (int q = 0; q < 2; q++)
                    #pragma unroll
                    for (int mt = 0; mt < 4; mt++)
                        mma16816(acc[mt][p*2+q], alo[mt], bh4 + q*2);
            }
        }
        stg++; if (stg >= 3) stg = 0;
    }

    #pragma unroll
    for (int mt = 0; mt < 4; mt++) {
        #pragma unroll
        for (int nt = 0; nt < 4; nt++) {
            int r0 = wm*64 + mt*16 + (lane >> 2);
            int c0 = wn*32 + nt*8 + (lane & 3)*2;
            #pragma unroll
            for (int half = 0; half < 2; half++) {
                int r = r0 + half*8;
                float d0 = acc[mt][nt][half*2];
                float d1 = acc[mt][nt][half*2 + 1];
                if (IS_FC) {
                    float wv = roww_s[r];
                    float v0 = fmaxf(d0, 0.0f); v0 = v0*v0*wv;
                    float v1 = fmaxf(d1, 0.0f); v1 = v1*v1*wv;
                    __nv_bfloat16 h0 = __float2bfloat16(v0);
                    __nv_bfloat16 l0 = __float2bfloat16(v0 - __bfloat162float(h0));
                    __nv_bfloat16 h1 = __float2bfloat16(v1);
                    __nv_bfloat16 l1 = __float2bfloat16(v1 - __bfloat162float(h1));
                    __nv_bfloat162 hh; hh.x = h0; hh.y = h1;
                    __nv_bfloat162 ll; ll.x = l0; ll.y = l1;
                    size_t base = (size_t)(slot0 + r)*HDIM + nb + c0;
                    *(__nv_bfloat162*)(g_hhi + base) = hh;
                    *(__nv_bfloat162*)(g_hlo + base) = ll;
                } else {
                    size_t base = (size_t)(slot0 + r)*DDIM + nb + c0;
                    float2 o; o.x = d0; o.y = d1;
                    *(float2*)(g_outslot + base) = o;
                }
            }
        }
    }
}

// ---------------- combine ----------------
__global__ void combine_kernel(float* __restrict__ out) {
    int n = blockIdx.x;
    int tid = threadIdx.x;
    int s0 = g_tokslot[n*2], s1 = g_tokslot[n*2+1];
    const float4* a = (const float4*)(g_outslot + (size_t)s0 * DDIM);
    const float4* b = (const float4*)(g_outslot + (size_t)s1 * DDIM);
    float4* o = (float4*)(out + (size_t)n * DDIM);
    for (int d = tid; d < DDIM/4; d += 256) {
        float4 av = a[d], bv = b[d];
        float4 ov;
        ov.x = av.x + bv.x; ov.y = av.y + bv.y;
        ov.z = av.z + bv.z; ov.w = av.w + bv.w;
        o[d] = ov;
    }
}

// ---------------- balance loss ----------------
__global__ void loss_kernel(float* __restrict__ out, int write_loss) {
    __shared__ float red[256];
    __shared__ float acc_sh;
    int tid = threadIdx.x;
    if (tid == 0) acc_sh = 0.0f;
    __syncthreads();
    for (int e = 0; e < NEXP; e++) {
        float s = 0.0f;
        for (int n = tid; n < NTOK; n += 256) s += g_probs[n*NEXP + e];
        red[tid] = s;
        __syncthreads();
        for (int o = 128; o; o >>= 1) {
            if (tid < o) red[tid] += red[tid + o];
            __syncthreads();
        }
        if (tid == 0) {
            float meanp = red[0] / (float)NTOK;
            float freq = (float)g_counts[e] / (float)NTOK;
            acc_sh += meanp * freq;
        }
        __syncthreads();
    }
    if (tid == 0 && write_loss)
        out[(size_t)NTOK * DDIM] = acc_sh * (float)NEXP;
}

// ---------------- launch ----------------
extern "C" void kernel_launch(void* const* d_in, const int* in_sizes, int n_in,
                              void* d_out, int out_size) {
    const float* x   = (const float*)d_in[0];
    const float* Wg  = (const float*)d_in[1];
    const float* Wfc = (const float*)d_in[2];
    const float* Wp  = (const float*)d_in[3];
    float* out = (float*)d_out;

    cudaFuncSetAttribute(mma_kernel<true>,  cudaFuncAttributeMaxDynamicSharedMemorySize, SM_MMA_TOTAL);
    cudaFuncSetAttribute(mma_kernel<false>, cudaFuncAttributeMaxDynamicSharedMemorySize, SM_MMA_TOTAL);

    __nv_bfloat16 *wfchi, *wfclo, *wphi, *wplo;
    cudaGetSymbolAddress((void**)&wfchi, g_wfchi);
    cudaGetSymbolAddress((void**)&wfclo, g_wfclo);
    cudaGetSymbolAddress((void**)&wphi,  g_wphi);
    cudaGetSymbolAddress((void**)&wplo,  g_wplo);

    int n4w = NEXP*HDIM*DDIM/4;          // 8388608
    int cvtBlocks = n4w/4/256;           // 8192 blocks; n4 == 4*S exactly

    // launch order: fc at index 3 (observed ncu capture point)
    cvt_kernel<<<cvtBlocks, 256>>>(Wfc, wfchi, wfclo, n4w);        // 0
    gate_kernel<<<NTOK, 256>>>(x, Wg);                             // 1
    route_kernel<<<1, 256>>>();                                    // 2
    dim3 gfc(MTILES, HDIM/128);
    mma_kernel<true><<<gfc, 256, SM_MMA_TOTAL>>>();                // 3
    cvt_kernel<<<cvtBlocks, 256>>>(Wp,  wphi,  wplo,  n4w);        // 4
    dim3 gpj(MTILES, DDIM/128);
    mma_kernel<false><<<gpj, 256, SM_MMA_TOTAL>>>();               // 5
    combine_kernel<<<NTOK, 256>>>(out);                            // 6
    int write_loss = (out_size > NTOK*DDIM) ? 1 : 0;
    loss_kernel<<<1, 256>>>(out, write_loss);                      // 7
}